// round 15
// baseline (speedup 1.0000x reference)
#include <cuda_runtime.h>
#include <cstdint>

typedef unsigned long long ull;

#define BMAX 2048
#define NSOM 148

// ---------------- device scratch ----------------
__device__ __align__(16) float g_feat[BMAX * 450];    // SOM features [b][450]
// weights interleaved [kg][j][og][4] per-layer (OPT: 4/2/2)
__device__ __align__(16) float g_W1t[120 * 4 * 100 * 4];  // k padded 450->480
__device__ __align__(16) float g_W2t[100 * 2 * 100 * 4];
__device__ __align__(16) float g_W3t[50 * 2 * 50 * 4];
__device__ __align__(16) float g_W4t[25 * 10 * 4];        // [kg][o][4]

// ---------------- f32x2 helpers ----------------
__device__ __forceinline__ ull ffma2(ull a, ull b, ull c) {
    ull d;
    asm("fma.rn.f32x2 %0, %1, %2, %3;" : "=l"(d) : "l"(a), "l"(b), "l"(c));
    return d;
}
__device__ __forceinline__ ull pack2(float lo, float hi) {
    ull r;
    asm("mov.b64 %0, {%1, %2};" : "=l"(r) : "f"(lo), "f"(hi));
    return r;
}
__device__ __forceinline__ float lo32(ull v) { return __uint_as_float((unsigned)v); }
__device__ __forceinline__ float hi32(ull v) { return __uint_as_float((unsigned)(v >> 32)); }

__device__ __forceinline__ void cp_async16(uint32_t saddr, const float* g) {
    asm volatile("cp.async.cg.shared.global [%0], [%1], 16;" :: "r"(saddr), "l"(g));
}
#define CP_COMMIT() asm volatile("cp.async.commit_group;")
#define CP_WAIT0()  asm volatile("cp.async.wait_group 0;")

// ---------------- Persistent SOM + inline prep slice ----------------
// 148 resident CTAs. Each: (a) 1/148 slice of weight interleave, (b) pack
// codebook ONCE, (c) loop over 512-patch tiles with cp.async double-buffered
// image prefetch overlapped with compute.
// smem: buf0[12288] | buf1[12288] | spkf[7168]  = 126976 B
__global__ __launch_bounds__(256, 1) void som_kernel(const float* __restrict__ x,
                                                     const float* __restrict__ somg,
                                                     const float* __restrict__ W1, const float* __restrict__ W2,
                                                     const float* __restrict__ W3, const float* __restrict__ W4,
                                                     int B, int ntiles) {
    extern __shared__ float sm[];
    float* bufs = sm;                          // 2 x 12288 floats
    float* spkf = sm + 24576;                  // paired codebook, 128*56 floats
    const double2* spk = (const double2*)spkf;
    int tid = threadIdx.x;

    // ---- prep slice (all CTAs; ~9 elems/thread) ----
    {
        int i0 = blockIdx.x * 256 + tid;
        int stride = NSOM * 256;
        for (int i = i0; i < 120 * 4 * 100 * 4; i += stride) {
            int kr = i & 3, r = i >> 2;
            int og = r % 100; r /= 100;
            int j = r & 3; int kg = r >> 2;
            int k = kg * 4 + kr, o = og * 4 + j;
            g_W1t[i] = (k < 450) ? W1[o * 450 + k] : 0.f;
        }
        for (int i = i0; i < 100 * 2 * 100 * 4; i += stride) {
            int kr = i & 3, r = i >> 2;
            int og = r % 100; r /= 100;
            int j = r & 1; int kg = r >> 1;
            g_W2t[i] = W2[(og * 2 + j) * 400 + kg * 4 + kr];
        }
        for (int i = i0; i < 50 * 2 * 50 * 4; i += stride) {
            int kr = i & 3, r = i >> 2;
            int og = r % 50; r /= 50;
            int j = r & 1; int kg = r >> 1;
            g_W3t[i] = W3[(og * 2 + j) * 200 + kg * 4 + kr];
        }
        for (int i = i0; i < 25 * 10 * 4; i += stride) {
            int kg = i / 40, r = i % 40, o = r >> 2, kr = r & 3;
            g_W4t[i] = W4[o * 100 + kg * 4 + kr];
        }
    }

    // ---- pack codebook once (pair-interleaved): thread c packs code c ----
    {
        int c = tid;
        int q = c >> 1, e = c & 1;
        float nrm = 0.f;
        const float* src = somg + c * 27;
#pragma unroll
        for (int k = 0; k < 27; k++) {
            float v = src[k];
            nrm += v * v;
            spkf[q * 56 + k * 2 + e] = v;
        }
        spkf[q * 56 + 54 + e] = -0.5f * nrm;
    }

    int total = B * 225;
    int t = blockIdx.x;
    if (t >= ntiles) { __syncthreads(); return; }

    uint32_t buf_s0 = (uint32_t)__cvta_generic_to_shared(bufs);

    // prologue: load tile t images into buffer 0
    {
        int i0 = (t * 512) / 225;
#pragma unroll
        for (int s = 0; s < 4; s++) {
            int img = i0 + s; if (img > B - 1) img = B - 1;
            const float* src = x + (size_t)img * 3072;
            uint32_t dst = buf_s0 + s * 3072 * 4;
            for (int i = tid; i < 768; i += 256) cp_async16(dst + i * 16, src + i * 4);
        }
        CP_COMMIT(); CP_WAIT0();
    }
    __syncthreads();

    int cur = 0;
#pragma unroll 1
    for (; t < ntiles; t += NSOM) {
        // prefetch next tile into other buffer
        int nt = t + NSOM;
        if (nt < ntiles) {
            int ni0 = (nt * 512) / 225;
            uint32_t dstb = buf_s0 + (1 - cur) * 12288 * 4;
#pragma unroll
            for (int s = 0; s < 4; s++) {
                int img = ni0 + s; if (img > B - 1) img = B - 1;
                const float* src = x + (size_t)img * 3072;
                uint32_t dst = dstb + s * 3072 * 4;
                for (int i = tid; i < 768; i += 256) cp_async16(dst + i * 16, src + i * 4);
            }
            CP_COMMIT();
        }

        // ---- compute tile t from bufs[cur] (R11 inner loop verbatim) ----
        {
            const float* simg = bufs + cur * 12288;
            int p0 = t * 512;
            int i0 = p0 / 225;

            int pA = p0 + tid;
            int pB = pA + 256;
            bool wA = pA < total, wB = pB < total;
            if (!wA) pA = total - 1;
            if (!wB) pB = pA;

            int imgA = pA / 225, tA = pA - imgA * 225;
            int imgB = pB / 225, tB = pB - imgB * 225;
            const float* baseA = simg + (imgA - i0) * 3072 + (tA / 15) * 64 + (tA % 15) * 2;
            const float* baseB = simg + (imgB - i0) * 3072 + (tB / 15) * 64 + (tB % 15) * 2;

            ull pa[27], pb[27];
#pragma unroll
            for (int c = 0; c < 3; c++)
#pragma unroll
                for (int i = 0; i < 3; i++)
#pragma unroll
                    for (int j = 0; j < 3; j++) {
                        float vA = baseA[c * 1024 + i * 32 + j];
                        float vB = baseB[c * 1024 + i * 32 + j];
                        pa[c * 9 + i * 3 + j] = pack2(vA, vA);
                        pb[c * 9 + i * 3 + j] = pack2(vB, vB);
                    }

            float bestA = -3.4e38f, bestB = -3.4e38f;
            int idxA = 0, idxB = 0;
#pragma unroll 2
            for (int q = 0; q < 128; q += 2) {
                const double2* P0 = spk + q * 14;
                const double2* P1 = P0 + 14;
                double2 t0 = P0[13], t1 = P1[13];
                ull n0 = (ull)__double_as_longlong(t0.y);
                ull n1 = (ull)__double_as_longlong(t1.y);
                ull c26_0 = (ull)__double_as_longlong(t0.x);
                ull c26_1 = (ull)__double_as_longlong(t1.x);
                ull a0 = ffma2(pa[26], c26_0, n0);
                ull a1 = ffma2(pa[26], c26_1, n1);
                ull b0 = ffma2(pb[26], c26_0, n0);
                ull b1 = ffma2(pb[26], c26_1, n1);
#pragma unroll
                for (int j = 0; j < 13; j++) {
                    double2 v0 = P0[j];
                    double2 v1 = P1[j];
                    ull w0 = (ull)__double_as_longlong(v0.x);
                    ull w1 = (ull)__double_as_longlong(v0.y);
                    ull w2 = (ull)__double_as_longlong(v1.x);
                    ull w3 = (ull)__double_as_longlong(v1.y);
                    a0 = ffma2(pa[2 * j],     w0, a0);
                    b0 = ffma2(pb[2 * j],     w0, b0);
                    a0 = ffma2(pa[2 * j + 1], w1, a0);
                    b0 = ffma2(pb[2 * j + 1], w1, b0);
                    a1 = ffma2(pa[2 * j],     w2, a1);
                    b1 = ffma2(pb[2 * j],     w2, b1);
                    a1 = ffma2(pa[2 * j + 1], w3, a1);
                    b1 = ffma2(pb[2 * j + 1], w3, b1);
                }
                float sA0 = lo32(a0), sA1 = hi32(a0), sA2 = lo32(a1), sA3 = hi32(a1);
                if (sA0 > bestA) { bestA = sA0; idxA = 2 * q; }
                if (sA1 > bestA) { bestA = sA1; idxA = 2 * q + 1; }
                if (sA2 > bestA) { bestA = sA2; idxA = 2 * q + 2; }
                if (sA3 > bestA) { bestA = sA3; idxA = 2 * q + 3; }
                float sB0 = lo32(b0), sB1 = hi32(b0), sB2 = lo32(b1), sB3 = hi32(b1);
                if (sB0 > bestB) { bestB = sB0; idxB = 2 * q; }
                if (sB1 > bestB) { bestB = sB1; idxB = 2 * q + 1; }
                if (sB2 > bestB) { bestB = sB2; idxB = 2 * q + 2; }
                if (sB3 > bestB) { bestB = sB3; idxB = 2 * q + 3; }
            }
            if (wA) {
                float* fb = g_feat + (size_t)imgA * 450;
                fb[tA]       = (float)(idxA >> 4) * 0.0625f;
                fb[225 + tA] = (float)(idxA & 15) * 0.0625f;
            }
            if (wB) {
                float* fb = g_feat + (size_t)imgB * 450;
                fb[tB]       = (float)(idxB >> 4) * 0.0625f;
                fb[225 + tB] = (float)(idxB & 15) * 0.0625f;
            }
        }

        CP_WAIT0();
        __syncthreads();
        cur = 1 - cur;
    }
}

// ---------------- MLP: R14 exact (lane-paired, 49.7us) ----------------
#define MTHREADS 256
#define NIMG 14
#define WBUF_U2 3200                // L1 chunk: 8 kg x 400 outs (51.2KB)

#define SA_U2 0                     // 120*14 = 1680 u2
#define SB_U2 1680                  // 100*14 = 1400 u2
#define SW_U2 3080
#define SM_U2 (3080 + 2 * WBUF_U2)  // 9480 u2 = 151.7KB

template <int NGK, int CK, int OPT, int NOG, int IMG, bool RELU>
__device__ __forceinline__ void layer(const float* __restrict__ Wg, const float* __restrict__ bias,
                                      const ulonglong2* sin, float* sout,
                                      ulonglong2* wbuf, uint32_t wbuf_s) {
    constexpr int CEF = CK * OPT * NOG * 4;   // floats per chunk
    constexpr int NCH = NGK / CK;             // exact
    int tid = threadIdx.x;

    for (int i = tid; i < CEF / 4; i += MTHREADS) cp_async16(wbuf_s + i * 16, Wg + i * 4);
    CP_COMMIT(); CP_WAIT0();
    __syncthreads();

    int og = tid >> 1, jg = tid & 1;          // lane-paired mapping
    bool active = og < NOG;
    ull acc[OPT * IMG];
#pragma unroll
    for (int i = 0; i < OPT * IMG; i++) acc[i] = 0;

#pragma unroll 1
    for (int c = 0; c < NCH; c++) {
        const ulonglong2* w = wbuf + (c & 1) * WBUF_U2;
        if (c + 1 < NCH) {
            uint32_t dst = wbuf_s + ((c + 1) & 1) * WBUF_U2 * 16;
            const float* src = Wg + (c + 1) * CEF;
            for (int i = tid; i < CEF / 4; i += MTHREADS) cp_async16(dst + i * 16, src + i * 4);
            CP_COMMIT();
        }
        if (active) {
#pragma unroll
            for (int kk = 0; kk < CK; kk++) {
                ulonglong2 av[IMG], wv[OPT];
#pragma unroll
                for (int i = 0; i < IMG; i++)
                    av[i] = sin[(c * CK + kk) * NIMG + jg * IMG + i];
#pragma unroll
                for (int j = 0; j < OPT; j++)
                    wv[j] = w[(kk * OPT + j) * NOG + og];
#pragma unroll
                for (int j = 0; j < OPT; j++)
#pragma unroll
                    for (int i = 0; i < IMG; i++) {
                        acc[j * IMG + i] = ffma2(av[i].x, wv[j].x, acc[j * IMG + i]);
                        acc[j * IMG + i] = ffma2(av[i].y, wv[j].y, acc[j * IMG + i]);
                    }
            }
        }
        CP_WAIT0();
        __syncthreads();
    }

    if (active) {
#pragma unroll
        for (int j = 0; j < OPT; j++) {
            int o = og * OPT + j;
            float bv = __ldg(bias + o);
#pragma unroll
            for (int i = 0; i < IMG; i++) {
                float v = lo32(acc[j * IMG + i]) + hi32(acc[j * IMG + i]) + bv;
                if (RELU) v = fmaxf(v, 0.f);
                int im = jg * IMG + i;
                sout[((o >> 2) * NIMG + im) * 4 + (o & 3)] = v;
            }
        }
    }
    __syncthreads();
}

__global__ __launch_bounds__(MTHREADS, 1) void mlp_kernel(const float* __restrict__ b1, const float* __restrict__ b2,
                                                          const float* __restrict__ b3, const float* __restrict__ b4,
                                                          float* __restrict__ out, int B) {
    extern __shared__ ulonglong2 smu[];
    ulonglong2* A = smu + SA_U2;
    ulonglong2* Bm = smu + SB_U2;
    ulonglong2* wbuf = smu + SW_U2;
    uint32_t wbuf_s = (uint32_t)__cvta_generic_to_shared(wbuf);
    int tid = threadIdx.x;
    int b0 = blockIdx.x * NIMG;

    // features -> A [kg][img(14)][4], zero-pad k >= 450
    float* Af = (float*)A;
    for (int i = tid; i < 120 * NIMG * 4; i += MTHREADS) {
        int kg = i / (NIMG * 4), r = i % (NIMG * 4), im = r >> 2, kr = r & 3;
        int k = kg * 4 + kr;
        int b = b0 + im; if (b > B - 1) b = B - 1;
        Af[i] = (k < 450) ? g_feat[(size_t)b * 450 + k] : 0.f;
    }
    __syncthreads();

    layer<120, 8, 4, 100, 7, true>(g_W1t, b1, A, (float*)Bm, wbuf, wbuf_s);   // 450->400
    layer<100, 10, 2, 100, 7, true>(g_W2t, b2, Bm, (float*)A, wbuf, wbuf_s);  // 400->200
    layer<50, 10, 2, 50, 7, true>(g_W3t, b3, A, (float*)Bm, wbuf, wbuf_s);    // 200->100

    // final 100 -> 10 (L1-resident __ldg weights)
    for (int job = tid; job < 10 * NIMG; job += MTHREADS) {
        int o = job % 10, im = job / 10;
        const ulonglong2* ar = Bm + im;
        ull acc = 0;
#pragma unroll
        for (int kg = 0; kg < 25; kg++) {
            ulonglong2 wv = __ldg((const ulonglong2*)g_W4t + kg * 10 + o);
            ulonglong2 av = ar[kg * NIMG];
            acc = ffma2(av.x, wv.x, acc);
            acc = ffma2(av.y, wv.y, acc);
        }
        int b = b0 + im;
        if (b < B) out[(size_t)b * 10 + o] = lo32(acc) + hi32(acc) + __ldg(b4 + o);
    }
}

// ---------------- launch ----------------
extern "C" void kernel_launch(void* const* d_in, const int* in_sizes, int n_in,
                              void* d_out, int out_size) {
    const float* x   = (const float*)d_in[0];
    const float* som = (const float*)d_in[1];
    const float* W1  = (const float*)d_in[2];
    const float* b1  = (const float*)d_in[3];
    const float* W2  = (const float*)d_in[4];
    const float* b2  = (const float*)d_in[5];
    const float* W3  = (const float*)d_in[6];
    const float* b3  = (const float*)d_in[7];
    const float* W4  = (const float*)d_in[8];
    const float* b4  = (const float*)d_in[9];
    float* out = (float*)d_out;

    int B = in_sizes[0] / 3072;
    if (B > BMAX) B = BMAX;

    int som_smem = 2 * 12288 * 4 + 128 * 56 * 4;   // 98304 + 28672 = 126976 B
    cudaFuncSetAttribute(som_kernel, cudaFuncAttributeMaxDynamicSharedMemorySize, som_smem);
    cudaFuncSetAttribute(mlp_kernel, cudaFuncAttributeMaxDynamicSharedMemorySize, SM_U2 * 16);

    int total_p = B * 225;
    int ntiles = (total_p + 511) / 512;
    som_kernel<<<NSOM, 256, som_smem>>>(x, som, W1, W2, W3, W4, B, ntiles);
    mlp_kernel<<<(B + NIMG - 1) / NIMG, MTHREADS, SM_U2 * 16>>>(b1, b2, b3, b4, out, B);
}

// round 16
// speedup vs baseline: 1.0035x; 1.0035x over previous
#include <cuda_runtime.h>
#include <cstdint>

typedef unsigned long long ull;

#define BMAX 2048
#define NPREP 128

// ---------------- device scratch ----------------
__device__ __align__(16) float g_feat[BMAX * 450];    // SOM features [b][450]
// weights interleaved per-layer: L1 [kg120][j2][og200][4]; L2 [kg100][og200][4];
// L3 [kg50][og100][4]; L4 [kg25][o10][4]
__device__ __align__(16) float g_W1t[120 * 2 * 200 * 4];  // k padded 450->480
__device__ __align__(16) float g_W2t[100 * 200 * 4];
__device__ __align__(16) float g_W3t[50 * 100 * 4];
__device__ __align__(16) float g_W4t[25 * 10 * 4];

// ---------------- f32x2 helpers ----------------
__device__ __forceinline__ ull ffma2(ull a, ull b, ull c) {
    ull d;
    asm("fma.rn.f32x2 %0, %1, %2, %3;" : "=l"(d) : "l"(a), "l"(b), "l"(c));
    return d;
}
__device__ __forceinline__ ull pack2(float lo, float hi) {
    ull r;
    asm("mov.b64 %0, {%1, %2};" : "=l"(r) : "f"(lo), "f"(hi));
    return r;
}
__device__ __forceinline__ float lo32(ull v) { return __uint_as_float((unsigned)v); }
__device__ __forceinline__ float hi32(ull v) { return __uint_as_float((unsigned)(v >> 32)); }

__device__ __forceinline__ void cp_async16(uint32_t saddr, const float* g) {
    asm volatile("cp.async.cg.shared.global [%0], [%1], 16;" :: "r"(saddr), "l"(g));
}
#define CP_COMMIT() asm volatile("cp.async.commit_group;")
#define CP_WAIT0()  asm volatile("cp.async.wait_group 0;")

// ---------------- SOM + weight-prep fused; PREP BLOCKS FIRST (R14 structure) ----------------
__global__ __launch_bounds__(256, 1) void som_kernel(const float* __restrict__ x,
                                                     const float* __restrict__ somg,
                                                     const float* __restrict__ W1, const float* __restrict__ W2,
                                                     const float* __restrict__ W3, const float* __restrict__ W4,
                                                     int B) {
    if (blockIdx.x < NPREP) {
        int i0 = blockIdx.x * 256 + threadIdx.x;
        int stride = NPREP * 256;
        // L1: [kg][j(2)][og(200)][4]
        for (int i = i0; i < 120 * 2 * 200 * 4; i += stride) {
            int kr = i & 3, r = i >> 2;
            int og = r % 200; r /= 200;
            int j = r & 1; int kg = r >> 1;
            int k = kg * 4 + kr, o = og * 2 + j;
            g_W1t[i] = (k < 450) ? W1[o * 450 + k] : 0.f;
        }
        // L2: [kg][og(200)][4]
        for (int i = i0; i < 100 * 200 * 4; i += stride) {
            int kr = i & 3, r = i >> 2;
            int og = r % 200; int kg = r / 200;
            g_W2t[i] = W2[og * 400 + kg * 4 + kr];
        }
        // L3: [kg][og(100)][4]
        for (int i = i0; i < 50 * 100 * 4; i += stride) {
            int kr = i & 3, r = i >> 2;
            int og = r % 100; int kg = r / 100;
            g_W3t[i] = W3[og * 200 + kg * 4 + kr];
        }
        for (int i = i0; i < 25 * 10 * 4; i += stride) {
            int kg = i / 40, r = i % 40, o = r >> 2, kr = r & 3;
            g_W4t[i] = W4[o * 100 + kg * 4 + kr];
        }
        return;
    }

    extern __shared__ float sm[];
    float* simg = sm;                          // 4 * 3072 floats
    float* spkf = sm + 12288;                  // paired codebook, 128*56 floats
    const double2* spk = (const double2*)spkf;

    int p0 = (blockIdx.x - NPREP) * 512;
    int i0 = p0 / 225;
    int total = B * 225;
#pragma unroll
    for (int s = 0; s < 4; s++) {
        int img = i0 + s; if (img > B - 1) img = B - 1;
        const float4* xb = (const float4*)(x + (size_t)img * 3072);
        float4* d = (float4*)(simg + s * 3072);
        for (int i = threadIdx.x; i < 768; i += 256) d[i] = xb[i];
    }
    {
        int c = threadIdx.x;
        int q = c >> 1, e = c & 1;
        float nrm = 0.f;
        const float* src = somg + c * 27;
#pragma unroll
        for (int k = 0; k < 27; k++) {
            float v = src[k];
            nrm += v * v;
            spkf[q * 56 + k * 2 + e] = v;
        }
        spkf[q * 56 + 54 + e] = -0.5f * nrm;
    }
    __syncthreads();

    int pA = p0 + threadIdx.x;
    int pB = pA + 256;
    bool wA = pA < total, wB = pB < total;
    if (!wA) pA = total - 1;
    if (!wB) pB = pA;

    int imgA = pA / 225, tA = pA - imgA * 225;
    int imgB = pB / 225, tB = pB - imgB * 225;
    const float* baseA = simg + (imgA - i0) * 3072 + (tA / 15) * 64 + (tA % 15) * 2;
    const float* baseB = simg + (imgB - i0) * 3072 + (tB / 15) * 64 + (tB % 15) * 2;

    ull pa[27], pb[27];
#pragma unroll
    for (int c = 0; c < 3; c++)
#pragma unroll
        for (int i = 0; i < 3; i++)
#pragma unroll
            for (int j = 0; j < 3; j++) {
                float vA = baseA[c * 1024 + i * 32 + j];
                float vB = baseB[c * 1024 + i * 32 + j];
                pa[c * 9 + i * 3 + j] = pack2(vA, vA);
                pb[c * 9 + i * 3 + j] = pack2(vB, vB);
            }

    float bestA = -3.4e38f, bestB = -3.4e38f;
    int idxA = 0, idxB = 0;
#pragma unroll 2
    for (int q = 0; q < 128; q += 2) {
        const double2* P0 = spk + q * 14;
        const double2* P1 = P0 + 14;
        double2 t0 = P0[13], t1 = P1[13];
        ull n0 = (ull)__double_as_longlong(t0.y);
        ull n1 = (ull)__double_as_longlong(t1.y);
        ull c26_0 = (ull)__double_as_longlong(t0.x);
        ull c26_1 = (ull)__double_as_longlong(t1.x);
        ull a0 = ffma2(pa[26], c26_0, n0);
        ull a1 = ffma2(pa[26], c26_1, n1);
        ull b0 = ffma2(pb[26], c26_0, n0);
        ull b1 = ffma2(pb[26], c26_1, n1);
#pragma unroll
        for (int j = 0; j < 13; j++) {
            double2 v0 = P0[j];
            double2 v1 = P1[j];
            ull w0 = (ull)__double_as_longlong(v0.x);
            ull w1 = (ull)__double_as_longlong(v0.y);
            ull w2 = (ull)__double_as_longlong(v1.x);
            ull w3 = (ull)__double_as_longlong(v1.y);
            a0 = ffma2(pa[2 * j],     w0, a0);
            b0 = ffma2(pb[2 * j],     w0, b0);
            a0 = ffma2(pa[2 * j + 1], w1, a0);
            b0 = ffma2(pb[2 * j + 1], w1, b0);
            a1 = ffma2(pa[2 * j],     w2, a1);
            b1 = ffma2(pb[2 * j],     w2, b1);
            a1 = ffma2(pa[2 * j + 1], w3, a1);
            b1 = ffma2(pb[2 * j + 1], w3, b1);
        }
        float sA0 = lo32(a0), sA1 = hi32(a0), sA2 = lo32(a1), sA3 = hi32(a1);
        if (sA0 > bestA) { bestA = sA0; idxA = 2 * q; }
        if (sA1 > bestA) { bestA = sA1; idxA = 2 * q + 1; }
        if (sA2 > bestA) { bestA = sA2; idxA = 2 * q + 2; }
        if (sA3 > bestA) { bestA = sA3; idxA = 2 * q + 3; }
        float sB0 = lo32(b0), sB1 = hi32(b0), sB2 = lo32(b1), sB3 = hi32(b1);
        if (sB0 > bestB) { bestB = sB0; idxB = 2 * q; }
        if (sB1 > bestB) { bestB = sB1; idxB = 2 * q + 1; }
        if (sB2 > bestB) { bestB = sB2; idxB = 2 * q + 2; }
        if (sB3 > bestB) { bestB = sB3; idxB = 2 * q + 3; }
    }
    if (wA) {
        float* fb = g_feat + (size_t)imgA * 450;
        fb[tA]       = (float)(idxA >> 4) * 0.0625f;
        fb[225 + tA] = (float)(idxA & 15) * 0.0625f;
    }
    if (wB) {
        float* fb = g_feat + (size_t)imgB * 450;
        fb[tB]       = (float)(idxB >> 4) * 0.0625f;
        fb[225 + tB] = (float)(idxB & 15) * 0.0625f;
    }
}

// ---------------- MLP: 7 imgs/CTA, grid 293, occ 2 (4 warps/SMSP) ----------------
// One image-group (IMG=7). og = tid directly; OPT outputs per job.
#define MTHREADS 256
#define NIMG 7
#define WBUF_U2 1600                // max chunk (L1: CK=4 x 2 x 200)

#define SA_U2 0                     // 120*7 = 840 u2
#define SB_U2 840                   // 100*7 = 700 u2
#define SW_U2 1540
#define SM_U2 (1540 + 2 * WBUF_U2)  // 4740 u2 = 75.8KB -> 2 CTAs/SM

template <int NGK, int CK, int OPT, int NOG, bool RELU>
__device__ __forceinline__ void layer(const float* __restrict__ Wg, const float* __restrict__ bias,
                                      const ulonglong2* sin, float* sout,
                                      ulonglong2* wbuf, uint32_t wbuf_s) {
    constexpr int CEF = CK * OPT * NOG * 4;   // floats per chunk
    constexpr int NCH = NGK / CK;             // exact
    int tid = threadIdx.x;

    for (int i = tid; i < CEF / 4; i += MTHREADS) cp_async16(wbuf_s + i * 16, Wg + i * 4);
    CP_COMMIT(); CP_WAIT0();
    __syncthreads();

    int og = tid;
    bool active = og < NOG;
    ull acc[OPT * NIMG];
#pragma unroll
    for (int i = 0; i < OPT * NIMG; i++) acc[i] = 0;

#pragma unroll 1
    for (int c = 0; c < NCH; c++) {
        const ulonglong2* w = wbuf + (c & 1) * WBUF_U2;
        if (c + 1 < NCH) {
            uint32_t dst = wbuf_s + ((c + 1) & 1) * WBUF_U2 * 16;
            const float* src = Wg + (c + 1) * CEF;
            for (int i = tid; i < CEF / 4; i += MTHREADS) cp_async16(dst + i * 16, src + i * 4);
            CP_COMMIT();
        }
        if (active) {
#pragma unroll
            for (int kk = 0; kk < CK; kk++) {
                ulonglong2 av[NIMG], wv[OPT];
#pragma unroll
                for (int i = 0; i < NIMG; i++)
                    av[i] = sin[(c * CK + kk) * NIMG + i];
#pragma unroll
                for (int j = 0; j < OPT; j++)
                    wv[j] = w[(kk * OPT + j) * NOG + og];
#pragma unroll
                for (int j = 0; j < OPT; j++)
#pragma unroll
                    for (int i = 0; i < NIMG; i++) {
                        acc[j * NIMG + i] = ffma2(av[i].x, wv[j].x, acc[j * NIMG + i]);
                        acc[j * NIMG + i] = ffma2(av[i].y, wv[j].y, acc[j * NIMG + i]);
                    }
            }
        }
        CP_WAIT0();
        __syncthreads();
    }

    if (active) {
#pragma unroll
        for (int j = 0; j < OPT; j++) {
            int o = og * OPT + j;
            float bv = __ldg(bias + o);
#pragma unroll
            for (int i = 0; i < NIMG; i++) {
                float v = lo32(acc[j * NIMG + i]) + hi32(acc[j * NIMG + i]) + bv;
                if (RELU) v = fmaxf(v, 0.f);
                sout[((o >> 2) * NIMG + i) * 4 + (o & 3)] = v;
            }
        }
    }
    __syncthreads();
}

__global__ __launch_bounds__(MTHREADS, 2) void mlp_kernel(const float* __restrict__ b1, const float* __restrict__ b2,
                                                          const float* __restrict__ b3, const float* __restrict__ b4,
                                                          float* __restrict__ out, int B) {
    extern __shared__ ulonglong2 smu[];
    ulonglong2* A = smu + SA_U2;
    ulonglong2* Bm = smu + SB_U2;
    ulonglong2* wbuf = smu + SW_U2;
    uint32_t wbuf_s = (uint32_t)__cvta_generic_to_shared(wbuf);
    int tid = threadIdx.x;
    int b0 = blockIdx.x * NIMG;

    // features -> A [kg][img(7)][4], zero-pad k >= 450
    float* Af = (float*)A;
    for (int i = tid; i < 120 * NIMG * 4; i += MTHREADS) {
        int kg = i / (NIMG * 4), r = i % (NIMG * 4), im = r >> 2, kr = r & 3;
        int k = kg * 4 + kr;
        int b = b0 + im; if (b > B - 1) b = B - 1;
        Af[i] = (k < 450) ? g_feat[(size_t)b * 450 + k] : 0.f;
    }
    __syncthreads();

    layer<120, 4, 2, 200, true>(g_W1t, b1, A, (float*)Bm, wbuf, wbuf_s);   // 450->400
    layer<100, 5, 1, 200, true>(g_W2t, b2, Bm, (float*)A, wbuf, wbuf_s);   // 400->200
    layer<50, 10, 1, 100, true>(g_W3t, b3, A, (float*)Bm, wbuf, wbuf_s);   // 200->100

    // final 100 -> 10 (L1-resident __ldg weights)
    for (int job = tid; job < 10 * NIMG; job += MTHREADS) {
        int o = job % 10, im = job / 10;
        const ulonglong2* ar = Bm + im;
        ull acc = 0;
#pragma unroll
        for (int kg = 0; kg < 25; kg++) {
            ulonglong2 wv = __ldg((const ulonglong2*)g_W4t + kg * 10 + o);
            ulonglong2 av = ar[kg * NIMG];
            acc = ffma2(av.x, wv.x, acc);
            acc = ffma2(av.y, wv.y, acc);
        }
        int b = b0 + im;
        if (b < B) out[(size_t)b * 10 + o] = lo32(acc) + hi32(acc) + __ldg(b4 + o);
    }
}

// ---------------- launch ----------------
extern "C" void kernel_launch(void* const* d_in, const int* in_sizes, int n_in,
                              void* d_out, int out_size) {
    const float* x   = (const float*)d_in[0];
    const float* som = (const float*)d_in[1];
    const float* W1  = (const float*)d_in[2];
    const float* b1  = (const float*)d_in[3];
    const float* W2  = (const float*)d_in[4];
    const float* b2  = (const float*)d_in[5];
    const float* W3  = (const float*)d_in[6];
    const float* b3  = (const float*)d_in[7];
    const float* W4  = (const float*)d_in[8];
    const float* b4  = (const float*)d_in[9];
    float* out = (float*)d_out;

    int B = in_sizes[0] / 3072;
    if (B > BMAX) B = BMAX;

    int som_smem = (4 * 3072) * 4 + 128 * 56 * 4;   // 77824 B
    cudaFuncSetAttribute(som_kernel, cudaFuncAttributeMaxDynamicSharedMemorySize, som_smem);
    cudaFuncSetAttribute(mlp_kernel, cudaFuncAttributeMaxDynamicSharedMemorySize, SM_U2 * 16);

    int total_p = B * 225;
    int nsom = (total_p + 511) / 512;
    som_kernel<<<NPREP + nsom, 256, som_smem>>>(x, som, W1, W2, W3, W4, B);
    mlp_kernel<<<(B + NIMG - 1) / NIMG, MTHREADS, SM_U2 * 16>>>(b1, b2, b3, b4, out, B);
}

// round 17
// speedup vs baseline: 1.1265x; 1.1225x over previous
#include <cuda_runtime.h>
#include <cstdint>

typedef unsigned long long ull;

#define BMAX 2048
#define NPREP 128

// ---------------- device scratch ----------------
__device__ __align__(16) float g_feat[BMAX * 450];    // SOM features [b][450]
// weights interleaved [kg][j][og][4] per-layer (OPT: 4/2/2)
__device__ __align__(16) float g_W1t[120 * 4 * 100 * 4];  // k padded 450->480
__device__ __align__(16) float g_W2t[100 * 2 * 100 * 4];
__device__ __align__(16) float g_W3t[50 * 2 * 50 * 4];
__device__ __align__(16) float g_W4t[25 * 10 * 4];        // [kg][o][4]

// ---------------- f32x2 helpers ----------------
__device__ __forceinline__ ull ffma2(ull a, ull b, ull c) {
    ull d;
    asm("fma.rn.f32x2 %0, %1, %2, %3;" : "=l"(d) : "l"(a), "l"(b), "l"(c));
    return d;
}
__device__ __forceinline__ ull pack2(float lo, float hi) {
    ull r;
    asm("mov.b64 %0, {%1, %2};" : "=l"(r) : "f"(lo), "f"(hi));
    return r;
}
__device__ __forceinline__ float lo32(ull v) { return __uint_as_float((unsigned)v); }
__device__ __forceinline__ float hi32(ull v) { return __uint_as_float((unsigned)(v >> 32)); }

__device__ __forceinline__ void cp_async16(uint32_t saddr, const float* g) {
    asm volatile("cp.async.cg.shared.global [%0], [%1], 16;" :: "r"(saddr), "l"(g));
}
#define CP_COMMIT() asm volatile("cp.async.commit_group;")
#define CP_WAIT0()  asm volatile("cp.async.wait_group 0;")

// ---------------- SOM + weight-prep fused; PREP BLOCKS FIRST ----------------
// smem: simg[12288f] | spkf[7168f] | raw[6912f] = 105472 B
// Images AND raw codebook staged via coalesced cp.async in ONE group; the
// pair-interleave pack then runs smem->smem (kills ~3us/CTA of uncoalesced LDG).
__global__ __launch_bounds__(256, 1) void som_kernel(const float* __restrict__ x,
                                                     const float* __restrict__ somg,
                                                     const float* __restrict__ W1, const float* __restrict__ W2,
                                                     const float* __restrict__ W3, const float* __restrict__ W4,
                                                     int B) {
    if (blockIdx.x < NPREP) {
        // ---- weight prep role (R14 exact) ----
        int i0 = blockIdx.x * 256 + threadIdx.x;
        int stride = NPREP * 256;
        for (int i = i0; i < 120 * 4 * 100 * 4; i += stride) {
            int kr = i & 3, r = i >> 2;
            int og = r % 100; r /= 100;
            int j = r & 3; int kg = r >> 2;
            int k = kg * 4 + kr, o = og * 4 + j;
            g_W1t[i] = (k < 450) ? W1[o * 450 + k] : 0.f;
        }
        for (int i = i0; i < 100 * 2 * 100 * 4; i += stride) {
            int kr = i & 3, r = i >> 2;
            int og = r % 100; r /= 100;
            int j = r & 1; int kg = r >> 1;
            g_W2t[i] = W2[(og * 2 + j) * 400 + kg * 4 + kr];
        }
        for (int i = i0; i < 50 * 2 * 50 * 4; i += stride) {
            int kr = i & 3, r = i >> 2;
            int og = r % 50; r /= 50;
            int j = r & 1; int kg = r >> 1;
            g_W3t[i] = W3[(og * 2 + j) * 200 + kg * 4 + kr];
        }
        for (int i = i0; i < 25 * 10 * 4; i += stride) {
            int kg = i / 40, r = i % 40, o = r >> 2, kr = r & 3;
            g_W4t[i] = W4[o * 100 + kg * 4 + kr];
        }
        return;
    }

    extern __shared__ float sm[];
    float* simg = sm;                          // 4 * 3072 floats
    float* spkf = sm + 12288;                  // paired codebook, 128*56 floats
    float* raw  = sm + 19456;                  // raw codebook, 256*27 floats
    const double2* spk = (const double2*)spkf;
    int tid = threadIdx.x;

    uint32_t simg_s = (uint32_t)__cvta_generic_to_shared(simg);
    uint32_t raw_s  = (uint32_t)__cvta_generic_to_shared(raw);

    int p0 = (blockIdx.x - NPREP) * 512;
    int i0 = p0 / 225;
    int total = B * 225;

    // stage images (coalesced cp.async)
#pragma unroll
    for (int s = 0; s < 4; s++) {
        int img = i0 + s; if (img > B - 1) img = B - 1;
        const float* src = x + (size_t)img * 3072;
        uint32_t dst = simg_s + s * 12288;
        for (int i = tid; i < 768; i += 256) cp_async16(dst + i * 16, src + i * 4);
    }
    // stage raw codebook (6912 floats = 1728 x 16B, coalesced)
    for (int i = tid; i < 1728; i += 256) cp_async16(raw_s + i * 16, somg + i * 4);
    CP_COMMIT(); CP_WAIT0();
    __syncthreads();

    // pack codebook smem->smem (pair-interleaved): thread c packs code c
    {
        int c = tid;
        int q = c >> 1, e = c & 1;
        float nrm = 0.f;
        const float* src = raw + c * 27;
#pragma unroll
        for (int k = 0; k < 27; k++) {
            float v = src[k];
            nrm += v * v;
            spkf[q * 56 + k * 2 + e] = v;
        }
        spkf[q * 56 + 54 + e] = -0.5f * nrm;
    }
    __syncthreads();

    int pA = p0 + tid;
    int pB = pA + 256;
    bool wA = pA < total, wB = pB < total;
    if (!wA) pA = total - 1;
    if (!wB) pB = pA;

    int imgA = pA / 225, tA = pA - imgA * 225;
    int imgB = pB / 225, tB = pB - imgB * 225;
    const float* baseA = simg + (imgA - i0) * 3072 + (tA / 15) * 64 + (tA % 15) * 2;
    const float* baseB = simg + (imgB - i0) * 3072 + (tB / 15) * 64 + (tB % 15) * 2;

    ull pa[27], pb[27];
#pragma unroll
    for (int c = 0; c < 3; c++)
#pragma unroll
        for (int i = 0; i < 3; i++)
#pragma unroll
            for (int j = 0; j < 3; j++) {
                float vA = baseA[c * 1024 + i * 32 + j];
                float vB = baseB[c * 1024 + i * 32 + j];
                pa[c * 9 + i * 3 + j] = pack2(vA, vA);
                pb[c * 9 + i * 3 + j] = pack2(vB, vB);
            }

    float bestA = -3.4e38f, bestB = -3.4e38f;
    int idxA = 0, idxB = 0;
#pragma unroll 2
    for (int q = 0; q < 128; q += 2) {
        const double2* P0 = spk + q * 14;
        const double2* P1 = P0 + 14;
        double2 t0 = P0[13], t1 = P1[13];
        ull n0 = (ull)__double_as_longlong(t0.y);
        ull n1 = (ull)__double_as_longlong(t1.y);
        ull c26_0 = (ull)__double_as_longlong(t0.x);
        ull c26_1 = (ull)__double_as_longlong(t1.x);
        ull a0 = ffma2(pa[26], c26_0, n0);
        ull a1 = ffma2(pa[26], c26_1, n1);
        ull b0 = ffma2(pb[26], c26_0, n0);
        ull b1 = ffma2(pb[26], c26_1, n1);
#pragma unroll
        for (int j = 0; j < 13; j++) {
            double2 v0 = P0[j];
            double2 v1 = P1[j];
            ull w0 = (ull)__double_as_longlong(v0.x);
            ull w1 = (ull)__double_as_longlong(v0.y);
            ull w2 = (ull)__double_as_longlong(v1.x);
            ull w3 = (ull)__double_as_longlong(v1.y);
            a0 = ffma2(pa[2 * j],     w0, a0);
            b0 = ffma2(pb[2 * j],     w0, b0);
            a0 = ffma2(pa[2 * j + 1], w1, a0);
            b0 = ffma2(pb[2 * j + 1], w1, b0);
            a1 = ffma2(pa[2 * j],     w2, a1);
            b1 = ffma2(pb[2 * j],     w2, b1);
            a1 = ffma2(pa[2 * j + 1], w3, a1);
            b1 = ffma2(pb[2 * j + 1], w3, b1);
        }
        float sA0 = lo32(a0), sA1 = hi32(a0), sA2 = lo32(a1), sA3 = hi32(a1);
        if (sA0 > bestA) { bestA = sA0; idxA = 2 * q; }
        if (sA1 > bestA) { bestA = sA1; idxA = 2 * q + 1; }
        if (sA2 > bestA) { bestA = sA2; idxA = 2 * q + 2; }
        if (sA3 > bestA) { bestA = sA3; idxA = 2 * q + 3; }
        float sB0 = lo32(b0), sB1 = hi32(b0), sB2 = lo32(b1), sB3 = hi32(b1);
        if (sB0 > bestB) { bestB = sB0; idxB = 2 * q; }
        if (sB1 > bestB) { bestB = sB1; idxB = 2 * q + 1; }
        if (sB2 > bestB) { bestB = sB2; idxB = 2 * q + 2; }
        if (sB3 > bestB) { bestB = sB3; idxB = 2 * q + 3; }
    }
    if (wA) {
        float* fb = g_feat + (size_t)imgA * 450;
        fb[tA]       = (float)(idxA >> 4) * 0.0625f;
        fb[225 + tA] = (float)(idxA & 15) * 0.0625f;
    }
    if (wB) {
        float* fb = g_feat + (size_t)imgB * 450;
        fb[tB]       = (float)(idxB >> 4) * 0.0625f;
        fb[225 + tB] = (float)(idxB & 15) * 0.0625f;
    }
}

// ---------------- MLP: R14 exact (lane-paired, 49.7us) ----------------
#define MTHREADS 256
#define NIMG 14
#define WBUF_U2 3200                // L1 chunk: 8 kg x 400 outs (51.2KB)

#define SA_U2 0                     // 120*14 = 1680 u2
#define SB_U2 1680                  // 100*14 = 1400 u2
#define SW_U2 3080
#define SM_U2 (3080 + 2 * WBUF_U2)  // 9480 u2 = 151.7KB

template <int NGK, int CK, int OPT, int NOG, int IMG, bool RELU>
__device__ __forceinline__ void layer(const float* __restrict__ Wg, const float* __restrict__ bias,
                                      const ulonglong2* sin, float* sout,
                                      ulonglong2* wbuf, uint32_t wbuf_s) {
    constexpr int CEF = CK * OPT * NOG * 4;   // floats per chunk
    constexpr int NCH = NGK / CK;             // exact
    int tid = threadIdx.x;

    for (int i = tid; i < CEF / 4; i += MTHREADS) cp_async16(wbuf_s + i * 16, Wg + i * 4);
    CP_COMMIT(); CP_WAIT0();
    __syncthreads();

    int og = tid >> 1, jg = tid & 1;          // lane-paired mapping
    bool active = og < NOG;
    ull acc[OPT * IMG];
#pragma unroll
    for (int i = 0; i < OPT * IMG; i++) acc[i] = 0;

#pragma unroll 1
    for (int c = 0; c < NCH; c++) {
        const ulonglong2* w = wbuf + (c & 1) * WBUF_U2;
        if (c + 1 < NCH) {
            uint32_t dst = wbuf_s + ((c + 1) & 1) * WBUF_U2 * 16;
            const float* src = Wg + (c + 1) * CEF;
            for (int i = tid; i < CEF / 4; i += MTHREADS) cp_async16(dst + i * 16, src + i * 4);
            CP_COMMIT();
        }
        if (active) {
#pragma unroll
            for (int kk = 0; kk < CK; kk++) {
                ulonglong2 av[IMG], wv[OPT];
#pragma unroll
                for (int i = 0; i < IMG; i++)
                    av[i] = sin[(c * CK + kk) * NIMG + jg * IMG + i];
#pragma unroll
                for (int j = 0; j < OPT; j++)
                    wv[j] = w[(kk * OPT + j) * NOG + og];
#pragma unroll
                for (int j = 0; j < OPT; j++)
#pragma unroll
                    for (int i = 0; i < IMG; i++) {
                        acc[j * IMG + i] = ffma2(av[i].x, wv[j].x, acc[j * IMG + i]);
                        acc[j * IMG + i] = ffma2(av[i].y, wv[j].y, acc[j * IMG + i]);
                    }
            }
        }
        CP_WAIT0();
        __syncthreads();
    }

    if (active) {
#pragma unroll
        for (int j = 0; j < OPT; j++) {
            int o = og * OPT + j;
            float bv = __ldg(bias + o);
#pragma unroll
            for (int i = 0; i < IMG; i++) {
                float v = lo32(acc[j * IMG + i]) + hi32(acc[j * IMG + i]) + bv;
                if (RELU) v = fmaxf(v, 0.f);
                int im = jg * IMG + i;
                sout[((o >> 2) * NIMG + im) * 4 + (o & 3)] = v;
            }
        }
    }
    __syncthreads();
}

__global__ __launch_bounds__(MTHREADS, 1) void mlp_kernel(const float* __restrict__ b1, const float* __restrict__ b2,
                                                          const float* __restrict__ b3, const float* __restrict__ b4,
                                                          float* __restrict__ out, int B) {
    extern __shared__ ulonglong2 smu[];
    ulonglong2* A = smu + SA_U2;
    ulonglong2* Bm = smu + SB_U2;
    ulonglong2* wbuf = smu + SW_U2;
    uint32_t wbuf_s = (uint32_t)__cvta_generic_to_shared(wbuf);
    int tid = threadIdx.x;
    int b0 = blockIdx.x * NIMG;

    // features -> A [kg][img(14)][4], zero-pad k >= 450
    float* Af = (float*)A;
    for (int i = tid; i < 120 * NIMG * 4; i += MTHREADS) {
        int kg = i / (NIMG * 4), r = i % (NIMG * 4), im = r >> 2, kr = r & 3;
        int k = kg * 4 + kr;
        int b = b0 + im; if (b > B - 1) b = B - 1;
        Af[i] = (k < 450) ? g_feat[(size_t)b * 450 + k] : 0.f;
    }
    __syncthreads();

    layer<120, 8, 4, 100, 7, true>(g_W1t, b1, A, (float*)Bm, wbuf, wbuf_s);   // 450->400
    layer<100, 10, 2, 100, 7, true>(g_W2t, b2, Bm, (float*)A, wbuf, wbuf_s);  // 400->200
    layer<50, 10, 2, 50, 7, true>(g_W3t, b3, A, (float*)Bm, wbuf, wbuf_s);    // 200->100

    // final 100 -> 10 (L1-resident __ldg weights)
    for (int job = tid; job < 10 * NIMG; job += MTHREADS) {
        int o = job % 10, im = job / 10;
        const ulonglong2* ar = Bm + im;
        ull acc = 0;
#pragma unroll
        for (int kg = 0; kg < 25; kg++) {
            ulonglong2 wv = __ldg((const ulonglong2*)g_W4t + kg * 10 + o);
            ulonglong2 av = ar[kg * NIMG];
            acc = ffma2(av.x, wv.x, acc);
            acc = ffma2(av.y, wv.y, acc);
        }
        int b = b0 + im;
        if (b < B) out[(size_t)b * 10 + o] = lo32(acc) + hi32(acc) + __ldg(b4 + o);
    }
}

// ---------------- launch ----------------
extern "C" void kernel_launch(void* const* d_in, const int* in_sizes, int n_in,
                              void* d_out, int out_size) {
    const float* x   = (const float*)d_in[0];
    const float* som = (const float*)d_in[1];
    const float* W1  = (const float*)d_in[2];
    const float* b1  = (const float*)d_in[3];
    const float* W2  = (const float*)d_in[4];
    const float* b2  = (const float*)d_in[5];
    const float* W3  = (const float*)d_in[6];
    const float* b3  = (const float*)d_in[7];
    const float* W4  = (const float*)d_in[8];
    const float* b4  = (const float*)d_in[9];
    float* out = (float*)d_out;

    int B = in_sizes[0] / 3072;
    if (B > BMAX) B = BMAX;

    int som_smem = (4 * 3072) * 4 + 128 * 56 * 4 + 256 * 27 * 4;  // 49152+28672+27648 = 105472 B
    cudaFuncSetAttribute(som_kernel, cudaFuncAttributeMaxDynamicSharedMemorySize, som_smem);
    cudaFuncSetAttribute(mlp_kernel, cudaFuncAttributeMaxDynamicSharedMemorySize, SM_U2 * 16);

    int total_p = B * 225;
    int nsom = (total_p + 511) / 512;
    som_kernel<<<NPREP + nsom, 256, som_smem>>>(x, som, W1, W2, W3, W4, B);
    mlp_kernel<<<(B + NIMG - 1) / NIMG, MTHREADS, SM_U2 * 16>>>(b1, b2, b3, b4, out, B);
}